// round 1
// baseline (speedup 1.0000x reference)
#include <cuda_runtime.h>

// Problem constants
#define NB    512       // batch B
#define NMF   256       // M features
#define RDIM  16
#define INDIM 50        // NMOD*R + 2
#define SROW  51        // padded S row (conflict-free smem)
#define OFF_U 512
#define OFF_S 25088     // 512 + 512*48
#define OFF_W 37888     // OFF_S + 256*50

// Scratch (transposed for coalesced reduction reads)
__device__ float g_ET [NMF*NB];
__device__ float g_EtT[NMF*NB];
__device__ float g_ExT[NMF*NB];
__device__ float g_GwT[512*NB];
__device__ float g_UvT[48*NB];

__device__ __forceinline__ float warp_sum(float v) {
#pragma unroll
    for (int o = 16; o; o >>= 1) v += __shfl_down_sync(0xffffffffu, v, o);
    return v;
}

// smem layout (floats): S[256*51] | inp[64] | cos[4*256] | sin[4*256] | esm[256] | red[16] | sc[32]
#define SMEM_FLOATS (NMF*SROW + 64 + 1024 + 1024 + 256 + 16 + 32)

__global__ __launch_bounds__(256) void fwd_kernel(
    const float* __restrict__ U0, const float* __restrict__ U1,
    const float* __restrict__ U2, const float* __restrict__ S,
    const float* __restrict__ w,  const float* __restrict__ tn,
    const float* __restrict__ obs, const int* __restrict__ idx,
    float* __restrict__ out)
{
    extern __shared__ float sm[];
    float* Ssm  = sm;                    // 256*51
    float* inp  = Ssm + NMF*SROW;        // 64 (uses 50)
    float* cosS = inp + 64;              // 4*256
    float* sinS = cosS + 1024;           // 4*256
    float* esm  = sinS + 1024;           // 256
    float* red  = esm + 256;             // 16
    float* sc   = red + 16;              // 32 scalars
    // sc: [0..3]=x stages, [4..7]=inp0 stages, [8..11]=k, [12..15]=J, [16..19]=chat, [20]=lam*A

    const int b    = blockIdx.x;
    const int t    = threadIdx.x;
    const int lane = t & 31, wid = t >> 5;

    // Load S coalesced into padded smem
    for (int i = t; i < NMF*INDIM; i += 256) {
        int m = i / INDIM;
        int j = i - m*INDIM;
        Ssm[m*SROW + j] = S[i];
    }
    // Gather Uvec (48 values) into inp[2..49]
    if (t < 48) {
        int v = t >> 4, r = t & 15;
        int iv = idx[b*3 + v];
        const float* Uv = (v == 0) ? U0 : (v == 1) ? U1 : U2;
        inp[2 + t] = Uv[iv*RDIM + r];
    }
    __syncthreads();

    const float scaleT = tn[b];
    const float wc = w[t], ws = w[256 + t];

    if (t == 0) {
        float beta = 0.f;
#pragma unroll
        for (int r = 0; r < 16; r++) beta += inp[2+r]*inp[18+r]*inp[34+r];
        sc[0] = beta;   // x at stage 0
        sc[4] = 0.f;    // inp0 at stage 0  (scaleT * t0, t0 = 0)
        inp[0] = 0.f;
        inp[1] = beta;
    }
    __syncthreads();

    // Per-thread constant part of phi (Uvec columns never change across stages)
    float phiU = 0.f;
#pragma unroll
    for (int j = 2; j < INDIM; j++) phiU = fmaf(Ssm[t*SROW + j], inp[j], phiU);
    const float s0 = Ssm[t*SROW + 0], s1 = Ssm[t*SROW + 1];

    // ---- RK4 stage loop (stages at t = 0, 0.5, 0.5, 1 ; h = 1) ----
    for (int i = 0; i < 4; i++) {
        float phi = phiU + s0*inp[0] + s1*inp[1];
        float cp, sp;
        sincosf(phi, &sp, &cp);
        cosS[i*256 + t] = cp;
        sinS[i*256 + t] = sp;
        float fp = cp*wc + sp*ws;          // contribution to f/scaleT
        float jp = (cp*ws - sp*wc) * s1;   // contribution to J/scaleT
        fp = warp_sum(fp);
        jp = warp_sum(jp);
        if (lane == 0) { red[wid] = fp; red[8 + wid] = jp; }
        __syncthreads();
        if (t == 0) {
            float F = 0.f, JJ = 0.f;
#pragma unroll
            for (int q = 0; q < 8; q++) { F += red[q]; JJ += red[8 + q]; }
            float k = scaleT * F;
            float J = scaleT * JJ;
            sc[8 + i]  = k;
            sc[12 + i] = J;
            float beta = sc[0];
            if (i < 3) {
                float xn = (i == 2) ? beta + k : beta + 0.5f*k;
                float tnext = (i == 2) ? 1.0f : 0.5f;
                inp[1] = xn;
                inp[0] = scaleT * tnext;
                sc[1 + i] = xn;        // x at stage i+1
                sc[5 + i] = inp[0];    // inp0 at stage i+1
            } else {
                float k1 = sc[8], k2 = sc[9], k3 = sc[10], k4 = k;
                float J1 = sc[12], J2 = sc[13], J3 = sc[14], J4 = J;
                float xT  = beta + (k1 + 2.f*k2 + 2.f*k3 + k4) * (1.f/6.f);
                float lam = (xT - obs[b]) * (1.f/512.f);
                float a1 = J1;
                float a2 = J2*(1.f + 0.5f*a1);
                float a3 = J3*(1.f + 0.5f*a2);
                float a4 = J4*(1.f + a3);
                float A  = 1.f + (a1 + 2.f*a2 + 2.f*a3 + a4) * (1.f/6.f);
                float c1 = (1.f + J2 + 0.5f*J3*J2 + 0.25f*J4*J3*J2) * (1.f/6.f);
                float c2 = (2.f + J3 + 0.5f*J4*J3) * (1.f/6.f);
                float c3 = (2.f + J4) * (1.f/6.f);
                float c4 = (1.f/6.f);
                float ls = lam * scaleT;
                sc[16] = ls*c1; sc[17] = ls*c2; sc[18] = ls*c3; sc[19] = ls*c4;
                sc[20] = lam * A;
                out[b] = lam * A;          // grad wrt beta (diagonal)
            }
        }
        __syncthreads();
    }

    // ---- pass 2: per-(b,m) weighted stage sums ----
    float e = 0.f, et = 0.f, ex = 0.f, gc = 0.f, gs = 0.f;
#pragma unroll
    for (int i = 0; i < 4; i++) {
        float ch = sc[16 + i];
        float cp = cosS[i*256 + t], sp = sinS[i*256 + t];
        float d  = cp*ws - sp*wc;
        float cd = ch * d;
        e  += cd;
        et += cd * sc[4 + i];   // * (scaleT * t_i)
        ex += cd * sc[0 + i];   // * x_i
        gc += ch * cp;
        gs += ch * sp;
    }
    g_ET [t*NB + b] = e;
    g_EtT[t*NB + b] = et;
    g_ExT[t*NB + b] = ex;
    g_GwT[t*NB + b]        = gc;
    g_GwT[(256 + t)*NB + b] = gs;
    esm[t] = e;
    if (t < 48) g_UvT[t*NB + b] = inp[2 + t];
    __syncthreads();

    // ---- per-b Uvec gradient: sum_m e_m * S[m, 2+j]  + beta-chain term ----
    float lamA = sc[20];
#pragma unroll
    for (int q = 0; q < 6; q++) {
        int j = wid*6 + q;
        float s = 0.f;
        for (int m = lane; m < NMF; m += 32)
            s += esm[m] * Ssm[m*SROW + 2 + j];
        s = warp_sum(s);
        if (lane == 0) {
            int v = j >> 4, r = j & 15;
            float u0 = inp[2 + r], u1 = inp[18 + r], u2 = inp[34 + r];
            float pe = (v == 0) ? u1*u2 : (v == 1) ? u0*u2 : u0*u1;
            out[OFF_U + b*48 + j] = s + lamA * pe;
        }
    }
}

// Cross-batch reductions: grad_S (256x50) and grad_w (512).
// blocks 0..63   : grad_S columns 2..49  (E^T @ Uv matmul, 4 m-rows per block, E tiled in smem)
// blocks 64..95  : grad_S columns 0,1    (sum of Et / Ex rows)
// blocks 96..111 : grad_w               (sum of Gw rows)
__global__ __launch_bounds__(256) void red_kernel(float* __restrict__ out)
{
    const int t = threadIdx.x, lane = t & 31, wid = t >> 5;
    const int bid = blockIdx.x;
    __shared__ float Esm[4 * NB];

    if (bid < 64) {
        int m0 = bid * 4;
        for (int i = t; i < 4*NB; i += 256) Esm[i] = g_ET[m0*NB + i];
        __syncthreads();
        // 192 (m_local, j) tasks over 8 warps
        for (int k = 0; k < 24; k++) {
            int task = wid + 8*k;
            int ml = task & 3;
            int j  = task >> 2;
            const float* Uv = g_UvT + j*NB;
            const float* E  = Esm + ml*NB;
            float s = 0.f;
#pragma unroll 4
            for (int bb = lane; bb < NB; bb += 32) s += E[bb] * Uv[bb];
            s = warp_sum(s);
            if (lane == 0) out[OFF_S + (m0 + ml)*INDIM + 2 + j] = s;
        }
    } else if (bid < 96) {
        int m = (bid - 64)*8 + wid;
        float st = 0.f, sx = 0.f;
        for (int bb = lane; bb < NB; bb += 32) {
            st += g_EtT[m*NB + bb];
            sx += g_ExT[m*NB + bb];
        }
        st = warp_sum(st);
        sx = warp_sum(sx);
        if (lane == 0) {
            out[OFF_S + m*INDIM + 0] = st;
            out[OFF_S + m*INDIM + 1] = sx;
        }
    } else {
        int q = bid - 96;   // 0..15
#pragma unroll
        for (int p = 0; p < 4; p++) {
            int row = q*32 + wid*4 + p;
            float s = 0.f;
            for (int bb = lane; bb < NB; bb += 32) s += g_GwT[row*NB + bb];
            s = warp_sum(s);
            if (lane == 0) out[OFF_W + row] = s;
        }
    }
}

extern "C" void kernel_launch(void* const* d_in, const int* in_sizes, int n_in,
                              void* d_out, int out_size)
{
    const float* U0  = (const float*)d_in[0];
    const float* U1  = (const float*)d_in[1];
    const float* U2  = (const float*)d_in[2];
    const float* S   = (const float*)d_in[3];
    const float* w   = (const float*)d_in[4];
    const float* tn  = (const float*)d_in[5];
    const float* obs = (const float*)d_in[6];
    const int*   idx = (const int*)d_in[7];
    float* out = (float*)d_out;

    const int smem_bytes = SMEM_FLOATS * (int)sizeof(float);
    cudaFuncSetAttribute(fwd_kernel, cudaFuncAttributeMaxDynamicSharedMemorySize, smem_bytes);

    fwd_kernel<<<NB, 256, smem_bytes>>>(U0, U1, U2, S, w, tn, obs, idx, out);
    red_kernel<<<112, 256>>>(out);
}

// round 3
// speedup vs baseline: 2.2416x; 2.2416x over previous
#include <cuda_runtime.h>

// Problem constants
#define NB    512       // batch B
#define NMF   256       // M features
#define RDIM  16
#define INDIM 50        // NMOD*R + 2
#define SROW  51        // padded S row (conflict-free smem)
#define OFF_U 512
#define OFF_S 25088     // 512 + 512*48
#define OFF_W 37888     // OFF_S + 256*50
#define G     4         // batch elements per fwd block
#define NBLK  (NB/G)    // 128 fwd blocks

// Scratch (row-per-output, b contiguous -> coalesced reduction reads)
__device__ float g_ET [NMF*NB];
__device__ float g_EtT[NMF*NB];
__device__ float g_ExT[NMF*NB];
__device__ float g_GwT[512*NB];
__device__ float g_UvT[48*NB];

__device__ __forceinline__ float warp_sum(float v) {
#pragma unroll
    for (int o = 16; o; o >>= 1) v += __shfl_down_sync(0xffffffffu, v, o);
    return v;
}

// smem floats: S[256*51] | inp[4*64] | cos[16*256] | sin[16*256] | esm[4*256] | red[64] | sc[4*32]
#define SMEM_FLOATS (NMF*SROW + G*64 + 4096 + 4096 + G*256 + 64 + G*32)

__global__ __launch_bounds__(256) void fwd_kernel(
    const float* __restrict__ U0, const float* __restrict__ U1,
    const float* __restrict__ U2, const float* __restrict__ S,
    const float* __restrict__ w,  const float* __restrict__ tn,
    const float* __restrict__ obs, const int* __restrict__ idx,
    float* __restrict__ out)
{
    extern __shared__ float sm[];
    float* Ssm  = sm;                    // 256*51
    float* inp  = Ssm + NMF*SROW;        // 4*64
    float* cosS = inp + G*64;            // [stage4][g4][256]
    float* sinS = cosS + 4096;
    float* esm  = sinS + 4096;           // [g][256]
    float* red  = esm + G*256;           // fp: g*8+wid, jp: 32 + g*8+wid
    float* sc   = red + 64;              // per g 32 scalars
    // sc[g*32+...]: [0..3]=x stages, [4..7]=inp0 stages, [8..11]=k, [12..15]=J,
    //               [16..19]=chat, [20]=lamA, [21]=scaleT

    const int b0   = blockIdx.x * G;
    const int t    = threadIdx.x;
    const int lane = t & 31, wid = t >> 5;

    // Load S coalesced into padded smem
    for (int i = t; i < NMF*INDIM; i += 256) {
        int m = i / INDIM;
        int j = i - m*INDIM;
        Ssm[m*SROW + j] = S[i];
    }
    // Gather Uvec (4 b x 48 values)
    if (t < G*48) {
        int g = t / 48, j = t - g*48;
        int v = j >> 4, r = j & 15;
        int iv = idx[(b0 + g)*3 + v];
        const float* Uv = (v == 0) ? U0 : (v == 1) ? U1 : U2;
        inp[g*64 + 2 + j] = Uv[iv*RDIM + r];
    }
    __syncthreads();

    if (t < G) {
        const int g = t;
        float* inpg = inp + g*64;
        float* scg  = sc + g*32;
        float beta = 0.f;
#pragma unroll
        for (int r = 0; r < 16; r++) beta += inpg[2+r]*inpg[18+r]*inpg[34+r];
        scg[0] = beta;           // x at stage 0
        scg[4] = 0.f;            // inp0 at stage 0
        scg[21] = tn[b0 + g];
        inpg[0] = 0.f;
        inpg[1] = beta;
    }
    __syncthreads();

    const float wc = w[t], ws = w[256 + t];
    const float s0 = Ssm[t*SROW + 0], s1 = Ssm[t*SROW + 1];

    // Per-thread constant part of phi (Uvec columns never change across stages)
    float phiU[G];
#pragma unroll
    for (int g = 0; g < G; g++) {
        float acc = 0.f;
#pragma unroll
        for (int j = 2; j < INDIM; j++) acc = fmaf(Ssm[t*SROW + j], inp[g*64 + j], acc);
        phiU[g] = acc;
    }

    // ---- RK4 stage loop (stages at t = 0, 0.5, 0.5, 1 ; h = 1) ----
    for (int i = 0; i < 4; i++) {
        float fp[G], jp[G];
#pragma unroll
        for (int g = 0; g < G; g++) {
            float phi = phiU[g] + s0*inp[g*64 + 0] + s1*inp[g*64 + 1];
            float cp, spv;
            sincosf(phi, &spv, &cp);
            cosS[(i*G + g)*256 + t] = cp;
            sinS[(i*G + g)*256 + t] = spv;
            fp[g] = cp*wc + spv*ws;
            jp[g] = (cp*ws - spv*wc) * s1;
        }
#pragma unroll
        for (int g = 0; g < G; g++) { fp[g] = warp_sum(fp[g]); jp[g] = warp_sum(jp[g]); }
        if (lane == 0) {
#pragma unroll
            for (int g = 0; g < G; g++) { red[g*8 + wid] = fp[g]; red[32 + g*8 + wid] = jp[g]; }
        }
        __syncthreads();
        if (t < G) {
            const int g = t;
            float* inpg = inp + g*64;
            float* scg  = sc + g*32;
            float F = 0.f, JJ = 0.f;
#pragma unroll
            for (int q = 0; q < 8; q++) { F += red[g*8 + q]; JJ += red[32 + g*8 + q]; }
            const float scaleT = scg[21];
            float k = scaleT * F;
            float J = scaleT * JJ;
            scg[8 + i]  = k;
            scg[12 + i] = J;
            float beta = scg[0];
            if (i < 3) {
                float xn = (i == 2) ? beta + k : beta + 0.5f*k;
                float tnext = (i == 2) ? 1.0f : 0.5f;
                inpg[1] = xn;
                inpg[0] = scaleT * tnext;
                scg[1 + i] = xn;
                scg[5 + i] = inpg[0];
            } else {
                float k1 = scg[8], k2 = scg[9], k3 = scg[10], k4 = k;
                float J1 = scg[12], J2 = scg[13], J3 = scg[14], J4 = J;
                float xT  = beta + (k1 + 2.f*k2 + 2.f*k3 + k4) * (1.f/6.f);
                float lam = (xT - obs[b0 + g]) * (1.f/512.f);
                float a1 = J1;
                float a2 = J2*(1.f + 0.5f*a1);
                float a3 = J3*(1.f + 0.5f*a2);
                float a4 = J4*(1.f + a3);
                float A  = 1.f + (a1 + 2.f*a2 + 2.f*a3 + a4) * (1.f/6.f);
                float c1 = (1.f + J2 + 0.5f*J3*J2 + 0.25f*J4*J3*J2) * (1.f/6.f);
                float c2 = (2.f + J3 + 0.5f*J4*J3) * (1.f/6.f);
                float c3 = (2.f + J4) * (1.f/6.f);
                float ls = lam * scaleT;
                scg[16] = ls*c1;
                scg[17] = ls*c2;
                scg[18] = ls*c3;
                scg[19] = ls*(1.f/6.f);
                scg[20] = lam * A;
                out[b0 + g] = lam * A;     // grad wrt beta (diagonal)
            }
        }
        __syncthreads();
    }

    // ---- pass 2: per-(b,m) weighted stage sums ----
    float eA[G], etA[G], exA[G], gcA[G], gsA[G];
#pragma unroll
    for (int g = 0; g < G; g++) {
        float e = 0.f, et = 0.f, ex = 0.f, gc = 0.f, gs = 0.f;
        const float* scg = sc + g*32;
#pragma unroll
        for (int i = 0; i < 4; i++) {
            float ch = scg[16 + i];
            float cp = cosS[(i*G + g)*256 + t], spv = sinS[(i*G + g)*256 + t];
            float d  = cp*ws - spv*wc;
            float cd = ch * d;
            e  += cd;
            et += cd * scg[4 + i];
            ex += cd * scg[0 + i];
            gc += ch * cp;
            gs += ch * spv;
        }
        eA[g] = e; etA[g] = et; exA[g] = ex; gcA[g] = gc; gsA[g] = gs;
        esm[g*256 + t] = e;
    }
    *(float4*)&g_ET [t*NB + b0] = make_float4(eA[0],  eA[1],  eA[2],  eA[3]);
    *(float4*)&g_EtT[t*NB + b0] = make_float4(etA[0], etA[1], etA[2], etA[3]);
    *(float4*)&g_ExT[t*NB + b0] = make_float4(exA[0], exA[1], exA[2], exA[3]);
    *(float4*)&g_GwT[t*NB + b0]         = make_float4(gcA[0], gcA[1], gcA[2], gcA[3]);
    *(float4*)&g_GwT[(256 + t)*NB + b0] = make_float4(gsA[0], gsA[1], gsA[2], gsA[3]);
    if (t < G*48) {
        int g = t / 48, j = t - g*48;
        g_UvT[j*NB + b0 + g] = inp[g*64 + 2 + j];
    }
    __syncthreads();

    // ---- per-b Uvec gradient: sum_m e_m * S[m, 2+j]  + beta-chain term ----
#pragma unroll
    for (int g = 0; g < G; g++) {
        const float lamA = sc[g*32 + 20];
        const float* eg = esm + g*256;
#pragma unroll
        for (int q = 0; q < 6; q++) {
            int j = wid*6 + q;
            float s = 0.f;
#pragma unroll
            for (int k = 0; k < 8; k++) {
                int m = lane + 32*k;
                s += eg[m] * Ssm[m*SROW + 2 + j];
            }
            s = warp_sum(s);
            if (lane == 0) {
                int v = j >> 4, r = j & 15;
                const float* inpg = inp + g*64;
                float u0 = inpg[2 + r], u1 = inpg[18 + r], u2 = inpg[34 + r];
                float pe = (v == 0) ? u1*u2 : (v == 1) ? u0*u2 : u0*u1;
                out[OFF_U + (b0 + g)*48 + j] = s + lamA * pe;
            }
        }
    }
}

// Cross-batch reductions: grad_S (256x50) and grad_w (512).
// blocks 0..255  : one S row m each: 48 matmul cols + col0 (Et) + col1 (Ex)
// blocks 256..319: grad_w, 8 rows each (one per warp)
__global__ __launch_bounds__(256) void red_kernel(float* __restrict__ out)
{
    const int t = threadIdx.x, lane = t & 31, wid = t >> 5;
    const int bid = blockIdx.x;
    __shared__ float Esm[NB];

    if (bid < NMF) {
        const int m = bid;
#pragma unroll
        for (int i = t; i < NB; i += 256) Esm[i] = g_ET[m*NB + i];
        __syncthreads();
        for (int task = wid; task < 50; task += 8) {
            float s = 0.f;
            if (task < 48) {
                const float* Uv = g_UvT + task*NB;
#pragma unroll
                for (int k = 0; k < 16; k++) s += Esm[lane + 32*k] * Uv[lane + 32*k];
                s = warp_sum(s);
                if (lane == 0) out[OFF_S + m*INDIM + 2 + task] = s;
            } else {
                const float* P = (task == 48) ? (g_EtT + m*NB) : (g_ExT + m*NB);
#pragma unroll
                for (int k = 0; k < 16; k++) s += P[lane + 32*k];
                s = warp_sum(s);
                if (lane == 0) out[OFF_S + m*INDIM + (task - 48)] = s;
            }
        }
    } else {
        const int row = (bid - NMF)*8 + wid;   // 0..511
        const float* P = g_GwT + row*NB;
        float s = 0.f;
#pragma unroll
        for (int k = 0; k < 16; k++) s += P[lane + 32*k];
        s = warp_sum(s);
        if (lane == 0) out[OFF_W + row] = s;
    }
}

extern "C" void kernel_launch(void* const* d_in, const int* in_sizes, int n_in,
                              void* d_out, int out_size)
{
    const float* U0  = (const float*)d_in[0];
    const float* U1  = (const float*)d_in[1];
    const float* U2  = (const float*)d_in[2];
    const float* S   = (const float*)d_in[3];
    const float* w   = (const float*)d_in[4];
    const float* tn  = (const float*)d_in[5];
    const float* obs = (const float*)d_in[6];
    const int*   idx = (const int*)d_in[7];
    float* out = (float*)d_out;

    const int smem_bytes = SMEM_FLOATS * (int)sizeof(float);
    cudaFuncSetAttribute(fwd_kernel, cudaFuncAttributeMaxDynamicSharedMemorySize, smem_bytes);

    fwd_kernel<<<NBLK, 256, smem_bytes>>>(U0, U1, U2, S, w, tn, obs, idx, out);
    red_kernel<<<NMF + 64, 256>>>(out);
}

// round 4
// speedup vs baseline: 2.7011x; 1.2050x over previous
#include <cuda_runtime.h>

// Problem constants
#define NB    512       // batch B
#define NMF   256       // M features
#define RDIM  16
#define INDIM 50        // NMOD*R + 2
#define SROW  51        // padded S row (conflict-free smem)
#define OFF_U 512
#define OFF_S 25088     // 512 + 512*48
#define OFF_W 37888     // OFF_S + 256*50
#define G     4         // batch elements per fwd block
#define NBLK  (NB/G)    // 128 fwd blocks

// Scratch (row-per-output, b contiguous -> coalesced reduction reads)
__device__ float g_ET [NMF*NB];
__device__ float g_EtT[NMF*NB];
__device__ float g_ExT[NMF*NB];
__device__ float g_GwT[512*NB];
__device__ float g_UvT[48*NB];

__device__ __forceinline__ float warp_sum(float v) {
#pragma unroll
    for (int o = 16; o; o >>= 1) v += __shfl_down_sync(0xffffffffu, v, o);
    return v;
}

// smem floats: S[256*51] | inp[4*64] | cos[16*256] | sin[16*256] | esm[4*256] | red[64] | sc[4*32]
#define SMEM_FLOATS (NMF*SROW + G*64 + 4096 + 4096 + G*256 + 64 + G*32)

// 512 threads: half = t>>8 handles g in {2*half, 2*half+1}; m = t & 255.
__global__ __launch_bounds__(512) void fwd_kernel(
    const float* __restrict__ U0, const float* __restrict__ U1,
    const float* __restrict__ U2, const float* __restrict__ S,
    const float* __restrict__ w,  const float* __restrict__ tn,
    const float* __restrict__ obs, const int* __restrict__ idx,
    float* __restrict__ out)
{
    extern __shared__ float sm[];
    float* Ssm  = sm;                    // 256*51
    float* inp  = Ssm + NMF*SROW;        // 4*64
    float* cosS = inp + G*64;            // [stage4][g4][256]
    float* sinS = cosS + 4096;
    float* esm  = sinS + 4096;           // [g][256]
    float* red  = esm + G*256;           // fp: g*8+w8, jp: 32 + g*8+w8
    float* sc   = red + 64;              // per g 32 scalars
    // sc[g*32+...]: [0..3]=x stages, [4..7]=inp0 stages, [8..11]=k, [12..15]=J,
    //               [16..19]=chat, [20]=lamA, [21]=scaleT

    const int b0   = blockIdx.x * G;
    const int t    = threadIdx.x;
    const int lane = t & 31;
    const int wid  = t >> 5;             // 0..15
    const int m    = t & 255;
    const int half = t >> 8;             // 0 or 1
    const int w8   = wid & 7;            // warp index within half

    // Load S via float4, scatter into padded smem rows
    {
        const float4* S4 = (const float4*)S;
        for (int i = t; i < (NMF*INDIM)/4; i += 512) {
            float4 v = S4[i];
            int base = i * 4;
#pragma unroll
            for (int c = 0; c < 4; c++) {
                int id = base + c;
                int mm = id / INDIM;
                int jj = id - mm*INDIM;
                float vc = (c == 0) ? v.x : (c == 1) ? v.y : (c == 2) ? v.z : v.w;
                Ssm[mm*SROW + jj] = vc;
            }
        }
    }
    // Gather Uvec (4 b x 48 values)
    if (t < G*48) {
        int g = t / 48, j = t - g*48;
        int v = j >> 4, r = j & 15;
        int iv = idx[(b0 + g)*3 + v];
        const float* Uv = (v == 0) ? U0 : (v == 1) ? U1 : U2;
        inp[g*64 + 2 + j] = Uv[iv*RDIM + r];
    }
    __syncthreads();

    if (t < G) {
        const int g = t;
        float* inpg = inp + g*64;
        float* scg  = sc + g*32;
        float beta = 0.f;
#pragma unroll
        for (int r = 0; r < 16; r++) beta += inpg[2+r]*inpg[18+r]*inpg[34+r];
        scg[0] = beta;           // x at stage 0
        scg[4] = 0.f;            // inp0 at stage 0
        scg[21] = tn[b0 + g];
        inpg[0] = 0.f;
        inpg[1] = beta;
    }
    __syncthreads();

    const float wc = w[m], ws = w[256 + m];
    const float s0 = Ssm[m*SROW + 0], s1 = Ssm[m*SROW + 1];
    const int g0 = half * 2;

    // Per-thread constant part of phi (Uvec columns never change across stages)
    float phiU[2];
#pragma unroll
    for (int gi = 0; gi < 2; gi++) {
        const int g = g0 + gi;
        float acc = 0.f;
#pragma unroll
        for (int j = 2; j < INDIM; j++) acc = fmaf(Ssm[m*SROW + j], inp[g*64 + j], acc);
        phiU[gi] = acc;
    }

    // ---- RK4 stage loop (stages at t = 0, 0.5, 0.5, 1 ; h = 1) ----
    for (int i = 0; i < 4; i++) {
        float fp[2], jp[2];
#pragma unroll
        for (int gi = 0; gi < 2; gi++) {
            const int g = g0 + gi;
            float phi = phiU[gi] + s0*inp[g*64 + 0] + s1*inp[g*64 + 1];
            float cp, spv;
            sincosf(phi, &spv, &cp);
            cosS[(i*G + g)*256 + m] = cp;
            sinS[(i*G + g)*256 + m] = spv;
            fp[gi] = cp*wc + spv*ws;
            jp[gi] = (cp*ws - spv*wc) * s1;
        }
#pragma unroll
        for (int gi = 0; gi < 2; gi++) { fp[gi] = warp_sum(fp[gi]); jp[gi] = warp_sum(jp[gi]); }
        if (lane == 0) {
#pragma unroll
            for (int gi = 0; gi < 2; gi++) {
                const int g = g0 + gi;
                red[g*8 + w8] = fp[gi];
                red[32 + g*8 + w8] = jp[gi];
            }
        }
        __syncthreads();
        if (t < G) {
            const int g = t;
            float* inpg = inp + g*64;
            float* scg  = sc + g*32;
            float F = 0.f, JJ = 0.f;
#pragma unroll
            for (int q = 0; q < 8; q++) { F += red[g*8 + q]; JJ += red[32 + g*8 + q]; }
            const float scaleT = scg[21];
            float k = scaleT * F;
            float J = scaleT * JJ;
            scg[8 + i]  = k;
            scg[12 + i] = J;
            float beta = scg[0];
            if (i < 3) {
                float xn = (i == 2) ? beta + k : beta + 0.5f*k;
                float tnext = (i == 2) ? 1.0f : 0.5f;
                inpg[1] = xn;
                inpg[0] = scaleT * tnext;
                scg[1 + i] = xn;
                scg[5 + i] = inpg[0];
            } else {
                float k1 = scg[8], k2 = scg[9], k3 = scg[10], k4 = k;
                float J1 = scg[12], J2 = scg[13], J3 = scg[14], J4 = J;
                float xT  = beta + (k1 + 2.f*k2 + 2.f*k3 + k4) * (1.f/6.f);
                float lam = (xT - obs[b0 + g]) * (1.f/512.f);
                float a1 = J1;
                float a2 = J2*(1.f + 0.5f*a1);
                float a3 = J3*(1.f + 0.5f*a2);
                float a4 = J4*(1.f + a3);
                float A  = 1.f + (a1 + 2.f*a2 + 2.f*a3 + a4) * (1.f/6.f);
                float c1 = (1.f + J2 + 0.5f*J3*J2 + 0.25f*J4*J3*J2) * (1.f/6.f);
                float c2 = (2.f + J3 + 0.5f*J4*J3) * (1.f/6.f);
                float c3 = (2.f + J4) * (1.f/6.f);
                float ls = lam * scaleT;
                scg[16] = ls*c1;
                scg[17] = ls*c2;
                scg[18] = ls*c3;
                scg[19] = ls*(1.f/6.f);
                scg[20] = lam * A;
                out[b0 + g] = lam * A;     // grad wrt beta (diagonal)
            }
        }
        __syncthreads();
    }

    // ---- pass 2: per-(b,m) weighted stage sums ----
    float eA[2], etA[2], exA[2], gcA[2], gsA[2];
#pragma unroll
    for (int gi = 0; gi < 2; gi++) {
        const int g = g0 + gi;
        float e = 0.f, et = 0.f, ex = 0.f, gc = 0.f, gs = 0.f;
        const float* scg = sc + g*32;
#pragma unroll
        for (int i = 0; i < 4; i++) {
            float ch = scg[16 + i];
            float cp = cosS[(i*G + g)*256 + m], spv = sinS[(i*G + g)*256 + m];
            float d  = cp*ws - spv*wc;
            float cd = ch * d;
            e  += cd;
            et += cd * scg[4 + i];
            ex += cd * scg[0 + i];
            gc += ch * cp;
            gs += ch * spv;
        }
        eA[gi] = e; etA[gi] = et; exA[gi] = ex; gcA[gi] = gc; gsA[gi] = gs;
        esm[g*256 + m] = e;
    }
    const int bo = b0 + 2*half;
    *(float2*)&g_ET [m*NB + bo] = make_float2(eA[0],  eA[1]);
    *(float2*)&g_EtT[m*NB + bo] = make_float2(etA[0], etA[1]);
    *(float2*)&g_ExT[m*NB + bo] = make_float2(exA[0], exA[1]);
    *(float2*)&g_GwT[m*NB + bo]         = make_float2(gcA[0], gcA[1]);
    *(float2*)&g_GwT[(256 + m)*NB + bo] = make_float2(gsA[0], gsA[1]);
    if (t < G*48) {
        int g = t / 48, j = t - g*48;
        g_UvT[j*NB + b0 + g] = inp[g*64 + 2 + j];
    }
    __syncthreads();

    // ---- per-b Uvec gradient: sum_m e_m * S[m, 2+j]  + beta-chain term ----
    // 16 warps x 12 tasks = 4 g x 48 j
    {
        const int g = wid >> 2;
        const int jbase = (wid & 3) * 12;
        const float lamA = sc[g*32 + 20];
        const float* eg = esm + g*256;
        const float* inpg = inp + g*64;
#pragma unroll
        for (int q = 0; q < 12; q++) {
            int j = jbase + q;
            float s = 0.f;
#pragma unroll
            for (int k = 0; k < 8; k++) {
                int mm = lane + 32*k;
                s += eg[mm] * Ssm[mm*SROW + 2 + j];
            }
            s = warp_sum(s);
            if (lane == 0) {
                int v = j >> 4, r = j & 15;
                float u0 = inpg[2 + r], u1 = inpg[18 + r], u2 = inpg[34 + r];
                float pe = (v == 0) ? u1*u2 : (v == 1) ? u0*u2 : u0*u1;
                out[OFF_U + (b0 + g)*48 + j] = s + lamA * pe;
            }
        }
    }
}

// Cross-batch reductions: grad_S (256x50) and grad_w (512).
// blocks 0..255  : one S row m each (512 thr): 48 matmul cols + Et + Ex, float4 loads
// blocks 256..287: grad_w, 16 rows each (one per warp)
__global__ __launch_bounds__(512) void red_kernel(float* __restrict__ out)
{
    const int t = threadIdx.x, lane = t & 31, wid = t >> 5;   // wid 0..15
    const int bid = blockIdx.x;
    __shared__ float Esm[NB];

    if (bid < NMF) {
        const int m = bid;
        Esm[t] = g_ET[m*NB + t];
        __syncthreads();
        const float4* E4 = (const float4*)Esm;
#pragma unroll
        for (int r = 0; r < 4; r++) {
            int task = wid + 16*r;
            if (task >= 50) break;
            float s = 0.f;
            if (task < 48) {
                const float4* Uv4 = (const float4*)(g_UvT + task*NB);
#pragma unroll
                for (int k = 0; k < 4; k++) {
                    float4 e = E4[lane + 32*k];
                    float4 u = Uv4[lane + 32*k];
                    s += e.x*u.x + e.y*u.y + e.z*u.z + e.w*u.w;
                }
                s = warp_sum(s);
                if (lane == 0) out[OFF_S + m*INDIM + 2 + task] = s;
            } else {
                const float4* P4 = (const float4*)((task == 48) ? (g_EtT + m*NB)
                                                                : (g_ExT + m*NB));
#pragma unroll
                for (int k = 0; k < 4; k++) {
                    float4 p = P4[lane + 32*k];
                    s += p.x + p.y + p.z + p.w;
                }
                s = warp_sum(s);
                if (lane == 0) out[OFF_S + m*INDIM + (task - 48)] = s;
            }
        }
    } else {
        const int row = (bid - NMF)*16 + wid;   // 0..511
        const float4* P4 = (const float4*)(g_GwT + row*NB);
        float s = 0.f;
#pragma unroll
        for (int k = 0; k < 4; k++) {
            float4 p = P4[lane + 32*k];
            s += p.x + p.y + p.z + p.w;
        }
        s = warp_sum(s);
        if (lane == 0) out[OFF_W + row] = s;
    }
}

extern "C" void kernel_launch(void* const* d_in, const int* in_sizes, int n_in,
                              void* d_out, int out_size)
{
    const float* U0  = (const float*)d_in[0];
    const float* U1  = (const float*)d_in[1];
    const float* U2  = (const float*)d_in[2];
    const float* S   = (const float*)d_in[3];
    const float* w   = (const float*)d_in[4];
    const float* tn  = (const float*)d_in[5];
    const float* obs = (const float*)d_in[6];
    const int*   idx = (const int*)d_in[7];
    float* out = (float*)d_out;

    const int smem_bytes = SMEM_FLOATS * (int)sizeof(float);
    cudaFuncSetAttribute(fwd_kernel, cudaFuncAttributeMaxDynamicSharedMemorySize, smem_bytes);

    fwd_kernel<<<NBLK, 512, smem_bytes>>>(U0, U1, U2, S, w, tn, obs, idx, out);
    red_kernel<<<NMF + 32, 512>>>(out);
}